// round 1
// baseline (speedup 1.0000x reference)
#include <cuda_runtime.h>
#include <math.h>

// Problem constants (from setup_inputs)
#define BQ 2
#define CC 64
#define LH 96
#define LW 96
#define HH 384
#define WW 384
#define DD 256
#define HW_LR (LH*LW)          // 9216
#define NPIX (BQ*HH*WW)        // 294912
#define CIN 266

// Scratch (device globals; no allocation allowed)
__device__ float g_P[(size_t)BQ*4*HW_LR*DD];   // [b][j][p][o]  ~75.5 MB
__device__ float g_sc[BQ*3*HW_LR];             // shortcut MLP output on LR grid
__device__ float g_b00c[DD];                   // b00 + cell-term (pixel-invariant)

// ---------------------------------------------------------------------------
// prep: fold constant rel_cell columns of w00 into the bias
__global__ void k_prep(const float* __restrict__ b00, const float* __restrict__ w00) {
    int o = threadIdx.x;
    if (o >= DD) return;
    float scale_h = (float)HH / (float)LH;
    float scale_w = (float)WW / (float)LW;
    float cell_h = (2.0f / (float)HH) * fmaxf(scale_h * 0.25f, 1.0f) * (float)LH;
    float cell_w = (2.0f / (float)WW) * fmaxf(scale_w * 0.25f, 1.0f) * (float)LW;
    g_b00c[o] = b00[o] + w00[o*CIN + 264] * cell_h + w00[o*CIN + 265] * cell_w;
}

// ---------------------------------------------------------------------------
// shortcut branch: sc = ws2 @ relu(ws1 @ feat + bs1) + bs2 per LR pixel
__global__ void k_short(const float* __restrict__ feat,
                        const float* __restrict__ ws1, const float* __restrict__ bs1,
                        const float* __restrict__ ws2, const float* __restrict__ bs2) {
    __shared__ float s_w1[64*64];
    __shared__ float s_w2[3*64];
    __shared__ float s_b[64];
    int tid = threadIdx.x;
    for (int i = tid; i < 4096; i += 128) s_w1[i] = ws1[i];
    for (int i = tid; i < 192;  i += 128) s_w2[i] = ws2[i];
    if (tid < 64) s_b[tid] = bs1[tid];
    __syncthreads();

    int p  = blockIdx.x * 128 + tid;        // 0..18431
    int b  = p / HW_LR;
    int pp = p - b * HW_LR;

    float f[64];
#pragma unroll
    for (int c = 0; c < 64; c++) f[c] = feat[(b*64 + c) * HW_LR + pp];

    float s0 = bs2[0], s1 = bs2[1], s2 = bs2[2];
#pragma unroll 4
    for (int co = 0; co < 64; co++) {
        float a = s_b[co];
#pragma unroll
        for (int c = 0; c < 64; c++) a += s_w1[co*64 + c] * f[c];
        a = fmaxf(a, 0.0f);
        s0 += s_w2[      co] * a;
        s1 += s_w2[ 64 + co] * a;
        s2 += s_w2[128 + co] * a;
    }
    g_sc[(b*3 + 0)*HW_LR + pp] = s0;
    g_sc[(b*3 + 1)*HW_LR + pp] = s1;
    g_sc[(b*3 + 2)*HW_LR + pp] = s2;
}

// ---------------------------------------------------------------------------
// precompute P[b][j][p][o] = sum_c W00[o][8 + 64j + c] * feat[b][c][p]
// grid: (144 p-tiles of 64, 4 j, 2 b), block 256
__global__ void k_pre(const float* __restrict__ feat, const float* __restrict__ w00) {
    extern __shared__ float sm[];
    float* fs  = sm;              // [64 c][64 px]
    float* wsb = sm + 64*64;      // [64 c][256 o]
    int tid = threadIdx.x;
    int p0 = blockIdx.x * 64;
    int j  = blockIdx.y;
    int b  = blockIdx.z;

    for (int e = tid; e < 64*64; e += 256) {
        int c = e >> 6, pp = e & 63;
        fs[c*64 + pp] = feat[(b*64 + c) * HW_LR + p0 + pp];
    }
    {
        int o = tid;
        const float* wr = w00 + o*CIN + 8 + j*64;
#pragma unroll
        for (int c = 0; c < 64; c++) wsb[c*256 + o] = wr[c];
    }
    __syncthreads();

    int lane = tid & 31, tp = tid >> 5;
    float acc[8][8];
#pragma unroll
    for (int i = 0; i < 8; i++)
#pragma unroll
        for (int r = 0; r < 8; r++) acc[i][r] = 0.0f;

#pragma unroll 4
    for (int c = 0; c < 64; c++) {
        float4 wlo = *(const float4*)&wsb[c*256 + lane*4];
        float4 whi = *(const float4*)&wsb[c*256 + 128 + lane*4];
#pragma unroll
        for (int i = 0; i < 8; i++) {
            float xv = fs[c*64 + tp*8 + i];
            acc[i][0] += wlo.x * xv; acc[i][1] += wlo.y * xv;
            acc[i][2] += wlo.z * xv; acc[i][3] += wlo.w * xv;
            acc[i][4] += whi.x * xv; acc[i][5] += whi.y * xv;
            acc[i][6] += whi.z * xv; acc[i][7] += whi.w * xv;
        }
    }
#pragma unroll
    for (int i = 0; i < 8; i++) {
        int p = p0 + tp*8 + i;
        float* dst = g_P + ((size_t)(b*4 + j) * HW_LR + p) * DD;
        *(float4*)&dst[lane*4]       = make_float4(acc[i][0], acc[i][1], acc[i][2], acc[i][3]);
        *(float4*)&dst[128 + lane*4] = make_float4(acc[i][4], acc[i][5], acc[i][6], acc[i][7]);
    }
}

// ---------------------------------------------------------------------------
// per-HR-pixel geometry (matches JAX reference incl. round-half-to-even)
__device__ __forceinline__ void pixel_geom(int y, int x, float rel[8], float aw[4], int pj[4]) {
    const float invH = 1.0f / (float)HH, invW = 1.0f / (float)WW;
    float cy = -1.0f + invH + (2.0f * invH) * (float)y;
    float cx = -1.0f + invW + (2.0f * invW) * (float)x;
    const float rx = 1.0f / (float)LH;   // shift along height
    const float ry = 1.0f / (float)LW;   // shift along width
    float area[4];
    int jj = 0;
#pragma unroll
    for (int a = 0; a < 2; a++) {
        float vx = a ? 1.0f : -1.0f;
#pragma unroll
        for (int bb = 0; bb < 2; bb++) {
            float vy = bb ? 1.0f : -1.0f;
            float sy = cy + vx * rx + 1e-6f;
            sy = fminf(fmaxf(sy, -1.0f + 1e-6f), 1.0f - 1e-6f);
            float sx = cx + vy * ry + 1e-6f;
            sx = fminf(fmaxf(sx, -1.0f + 1e-6f), 1.0f - 1e-6f);
            float uy = ((sy + 1.0f) * (float)LH - 1.0f) * 0.5f;
            float ux = ((sx + 1.0f) * (float)LW - 1.0f) * 0.5f;
            int iy = min(max(__float2int_rn(uy), 0), LH - 1);
            int ix = min(max(__float2int_rn(ux), 0), LW - 1);
            float oy = -1.0f + 1.0f/(float)LH + (2.0f/(float)LH) * (float)iy;
            float ox = -1.0f + 1.0f/(float)LW + (2.0f/(float)LW) * (float)ix;
            float rly = (cy - oy) * (float)LH;
            float rlx = (cx - ox) * (float)LW;
            rel[2*jj]   = rly;
            rel[2*jj+1] = rlx;
            area[jj] = fabsf(rly * rlx) + 1e-9f;
            pj[jj] = iy * LW + ix;
            jj++;
        }
    }
    float tot = area[0] + area[1] + area[2] + area[3];
    float inv = 1.0f / tot;
    aw[0] = area[3] * inv;   // LIIF swap 0<->3, 1<->2
    aw[1] = area[2] * inv;
    aw[2] = area[1] * inv;
    aw[3] = area[0] * inv;
}

__device__ __forceinline__ float gelu_exact(float v) {
    return 0.5f * v * (1.0f + erff(v * 0.70710678118654752f));
}

// ---------------------------------------------------------------------------
// main fused kernel: gather-P -> x ; t = gelu(W1 x + b1) ; out = W2 t + b2 + shortcut
// block = 256 threads, 64 HR pixels per CTA (contiguous along x; 384 = 6*64)
#define XS_STRIDE 260
__global__ __launch_bounds__(256, 2) void k_main(
        const float* __restrict__ w00,
        const float* __restrict__ w1, const float* __restrict__ b1,
        const float* __restrict__ w2, const float* __restrict__ b2,
        float* __restrict__ out) {
    extern __shared__ float sm[];
    float* xs  = sm;                       // [64 px][260]  (x, later t)
    float* wst = sm + 64*XS_STRIDE;        // [16 k][256 o]
    float* w8s = wst + 16*256;             // [8 k][256 o]  (rel columns of w00)

    int tid = threadIdx.x, lane = tid & 31, wid = tid >> 5;
    int pbase = blockIdx.x * 64;

    // stage 0: load w00 rel columns (transposed), b00c into regs
    {
        int o = tid;
#pragma unroll
        for (int k = 0; k < 8; k++) w8s[k*256 + o] = w00[o*CIN + k];
    }
    float4 bclo = *(const float4*)&g_b00c[lane*4];
    float4 bchi = *(const float4*)&g_b00c[128 + lane*4];
    float4 b1lo = *(const float4*)&b1[lane*4];
    float4 b1hi = *(const float4*)&b1[128 + lane*4];
    __syncthreads();

    // stage 1: each warp computes x for its 8 pixels (o = lane*4..+3, 128+lane*4..+3)
    for (int i = 0; i < 8; i++) {
        int pl = wid*8 + i;
        int g  = pbase + pl;
        int b  = g / (HH*WW);
        int r  = g - b*(HH*WW);
        int y  = r / WW;
        int x  = r - y*WW;
        float rel[8], aw[4];
        int pj[4];
        pixel_geom(y, x, rel, aw, pj);

        float a0 = bclo.x, a1 = bclo.y, a2 = bclo.z, a3 = bclo.w;
        float a4 = bchi.x, a5 = bchi.y, a6 = bchi.z, a7 = bchi.w;
#pragma unroll
        for (int j = 0; j < 4; j++) {
            const float* Pp = g_P + ((size_t)(b*4 + j) * HW_LR + pj[j]) * DD;
            float4 lo = __ldg((const float4*)&Pp[lane*4]);
            float4 hi = __ldg((const float4*)&Pp[128 + lane*4]);
            float s = aw[j];
            a0 += s*lo.x; a1 += s*lo.y; a2 += s*lo.z; a3 += s*lo.w;
            a4 += s*hi.x; a5 += s*hi.y; a6 += s*hi.z; a7 += s*hi.w;
        }
#pragma unroll
        for (int k = 0; k < 8; k++) {
            float rv = rel[k];
            float4 wlo = *(const float4*)&w8s[k*256 + lane*4];
            float4 whi = *(const float4*)&w8s[k*256 + 128 + lane*4];
            a0 += wlo.x*rv; a1 += wlo.y*rv; a2 += wlo.z*rv; a3 += wlo.w*rv;
            a4 += whi.x*rv; a5 += whi.y*rv; a6 += whi.z*rv; a7 += whi.w*rv;
        }
        *(float4*)&xs[pl*XS_STRIDE + lane*4]       = make_float4(a0, a1, a2, a3);
        *(float4*)&xs[pl*XS_STRIDE + 128 + lane*4] = make_float4(a4, a5, a6, a7);
    }
    __syncthreads();

    // stage 2: t = gelu(W1 @ x + b1), 64px x 256o GEMM, K=256
    int tp = wid;  // pixel group = warp id (warp-private rows of xs)
    float acc[8][8];
#pragma unroll
    for (int i = 0; i < 8; i++)
#pragma unroll
        for (int rr = 0; rr < 8; rr++) acc[i][rr] = 0.0f;

    for (int kc = 0; kc < 256; kc += 16) {
        const float* wr = w1 + tid*256 + kc;
        float4 q0 = *(const float4*)&wr[0];
        float4 q1 = *(const float4*)&wr[4];
        float4 q2 = *(const float4*)&wr[8];
        float4 q3 = *(const float4*)&wr[12];
        __syncthreads();
        wst[ 0*256 + tid] = q0.x; wst[ 1*256 + tid] = q0.y;
        wst[ 2*256 + tid] = q0.z; wst[ 3*256 + tid] = q0.w;
        wst[ 4*256 + tid] = q1.x; wst[ 5*256 + tid] = q1.y;
        wst[ 6*256 + tid] = q1.z; wst[ 7*256 + tid] = q1.w;
        wst[ 8*256 + tid] = q2.x; wst[ 9*256 + tid] = q2.y;
        wst[10*256 + tid] = q2.z; wst[11*256 + tid] = q2.w;
        wst[12*256 + tid] = q3.x; wst[13*256 + tid] = q3.y;
        wst[14*256 + tid] = q3.z; wst[15*256 + tid] = q3.w;
        __syncthreads();

#pragma unroll
        for (int ki = 0; ki < 16; ki++) {
            float4 wlo = *(const float4*)&wst[ki*256 + lane*4];
            float4 whi = *(const float4*)&wst[ki*256 + 128 + lane*4];
#pragma unroll
            for (int i = 0; i < 8; i++) {
                float xv = xs[(tp*8 + i)*XS_STRIDE + kc + ki];
                acc[i][0] += wlo.x*xv; acc[i][1] += wlo.y*xv;
                acc[i][2] += wlo.z*xv; acc[i][3] += wlo.w*xv;
                acc[i][4] += whi.x*xv; acc[i][5] += whi.y*xv;
                acc[i][6] += whi.z*xv; acc[i][7] += whi.w*xv;
            }
        }
    }
    __syncwarp();   // all lanes of this warp done reading their xs rows
#pragma unroll
    for (int i = 0; i < 8; i++) {
        int px = tp*8 + i;
        float v0 = gelu_exact(acc[i][0] + b1lo.x);
        float v1 = gelu_exact(acc[i][1] + b1lo.y);
        float v2 = gelu_exact(acc[i][2] + b1lo.z);
        float v3 = gelu_exact(acc[i][3] + b1lo.w);
        float v4 = gelu_exact(acc[i][4] + b1hi.x);
        float v5 = gelu_exact(acc[i][5] + b1hi.y);
        float v6 = gelu_exact(acc[i][6] + b1hi.z);
        float v7 = gelu_exact(acc[i][7] + b1hi.w);
        *(float4*)&xs[px*XS_STRIDE + lane*4]       = make_float4(v0, v1, v2, v3);
        *(float4*)&xs[px*XS_STRIDE + 128 + lane*4] = make_float4(v4, v5, v6, v7);
    }
    __syncthreads();

    // stage 3: out = W2 @ t + b2 + bilinear(shortcut)
    if (tid < 192) {
        int idx = tid;
        int px = idx / 3;
        int c  = idx - px*3;
        int g  = pbase + px;
        int b  = g / (HH*WW);
        int r  = g - b*(HH*WW);
        int y  = r / WW;
        int x  = r - y*WW;

        const float* wr = w2 + c*256;
        const float* tr = xs + px*XS_STRIDE;
        float dot = b2[c];
#pragma unroll 8
        for (int k = 0; k < 256; k += 4) {
            float4 wv = *(const float4*)&wr[k];
            float4 tv = *(const float4*)&tr[k];
            dot += wv.x*tv.x + wv.y*tv.y + wv.z*tv.z + wv.w*tv.w;
        }

        float cy = -1.0f + 1.0f/(float)HH + (2.0f/(float)HH) * (float)y;
        float cx = -1.0f + 1.0f/(float)WW + (2.0f/(float)WW) * (float)x;
        float uy = ((cy + 1.0f) * (float)LH - 1.0f) * 0.5f;
        float ux = ((cx + 1.0f) * (float)LW - 1.0f) * 0.5f;
        float y0f = floorf(uy), x0f = floorf(ux);
        float wy = uy - y0f, wx = ux - x0f;
        int y0 = min(max((int)y0f, 0), LH-1);
        int y1 = min(max((int)y0f + 1, 0), LH-1);
        int x0 = min(max((int)x0f, 0), LW-1);
        int x1 = min(max((int)x0f + 1, 0), LW-1);
        const float* scb = g_sc + (b*3 + c) * HW_LR;
        float samp = scb[y0*LW + x0] * ((1.0f - wy)*(1.0f - wx))
                   + scb[y0*LW + x1] * ((1.0f - wy)*wx)
                   + scb[y1*LW + x0] * (wy*(1.0f - wx))
                   + scb[y1*LW + x1] * (wy*wx);

        out[((size_t)(b*3 + c) * HH + y) * WW + x] = dot + samp;
    }
}

// ---------------------------------------------------------------------------
extern "C" void kernel_launch(void* const* d_in, const int* in_sizes, int n_in,
                              void* d_out, int out_size) {
    const float* feat = (const float*)d_in[0];
    const float* w00  = (const float*)d_in[1];
    const float* b00  = (const float*)d_in[2];
    const float* w1   = (const float*)d_in[3];
    const float* b1   = (const float*)d_in[4];
    const float* w2   = (const float*)d_in[5];
    const float* b2   = (const float*)d_in[6];
    const float* ws1  = (const float*)d_in[7];
    const float* bs1  = (const float*)d_in[8];
    const float* ws2  = (const float*)d_in[9];
    const float* bs2  = (const float*)d_in[10];
    float* out = (float*)d_out;

    static bool attr_done = false;
    size_t smemB = (size_t)(64*64 + 64*256) * sizeof(float);                 // 80 KB
    size_t smemC = (size_t)(64*XS_STRIDE + 16*256 + 8*256) * sizeof(float);  // ~89 KB
    if (!attr_done) {
        cudaFuncSetAttribute(k_pre,  cudaFuncAttributeMaxDynamicSharedMemorySize, (int)smemB);
        cudaFuncSetAttribute(k_main, cudaFuncAttributeMaxDynamicSharedMemorySize, (int)smemC);
        attr_done = true;
    }

    k_prep<<<1, 256>>>(b00, w00);
    k_short<<<HW_LR*BQ/128, 128>>>(feat, ws1, bs1, ws2, bs2);
    k_pre<<<dim3(HW_LR/64, 4, BQ), 256, smemB>>>(feat, w00);
    k_main<<<NPIX/64, 256, smemC>>>(w00, w1, b1, w2, b2, out);
}